// round 8
// baseline (speedup 1.0000x reference)
#include <cuda_runtime.h>
#include <cstdint>

// ---------------------------------------------------------------------------
// CRF Viterbi decode, K=16 tags, T up to 1,000,000 steps.
//
// Pipeline:
//   K1 k_chain : sequential bit-exact forward recurrence (1 warp, 16 lanes),
//                stores fv trace [T][16] fp32.
//   K2 k_bp    : grid-parallel backpointers from fv trace (first-max argmax).
//   K3 k_chunk : per-chunk 16-hypothesis backward chase -> path16 + comp maps.
//   K3b k_seed : sequential composition of chunk maps (tiny), picks seeds.
//   K4 k_out   : parallel select of final path — written as FLOAT32
//                (harness compares the output as fp32; int bit patterns are
//                denormals ~0 which produced the exact-1.0 rel_err signature).
//
// Inputs autodetected by element count: 256-element tensor = transitions
// [16,16]; large tensor = sentence [1,T,16].
// ---------------------------------------------------------------------------

#define T_MAX   1000000
#define KT      16
#define CHUNK   1024
#define NCHUNK_MAX ((T_MAX + CHUNK - 1) / CHUNK)   // 977
#define PF      16                                  // feat prefetch depth

__device__ __align__(16) float         g_fv[(size_t)T_MAX * KT];   // 64 MB
__device__ __align__(16) unsigned char g_bp[(size_t)T_MAX * KT];   // 16 MB
__device__ __align__(16) unsigned char g_p16[(size_t)T_MAX * KT];  // 16 MB
__device__ __align__(16) unsigned char g_comp[NCHUNK_MAX * KT];
__device__ __align__(16) unsigned char g_seed[NCHUNK_MAX];

// ---------------------------------------------------------------------------
// K1: the sequential value chain. Lane j (0..15) owns tag j.
//   fv_t[j] = max_p( fv_{t-1}[p] + A[j][p] ) + feat_t[j]
// Bit-exact vs reference: one FADD per score, exact max, one FADD for feat.
// ---------------------------------------------------------------------------
__global__ void __launch_bounds__(16, 1)
k_chain(const float* __restrict__ feats, const float* __restrict__ trans, int T)
{
    const int j = threadIdx.x;            // 0..15, tag index
    const unsigned MASK = 0xFFFFu;

    // A row j (transitions[next=j][prev=p]) -> registers
    float a[16];
#pragma unroll
    for (int q = 0; q < 4; q++) {
        float4 v = reinterpret_cast<const float4*>(trans)[j * 4 + q];
        a[4 * q + 0] = v.x; a[4 * q + 1] = v.y;
        a[4 * q + 2] = v.z; a[4 * q + 3] = v.w;
    }

    // Feat software pipeline: PF steps ahead (~800 cyc > DRAM latency)
    float fq[PF];
#pragma unroll
    for (int u = 0; u < PF; u++)
        fq[u] = (u < T) ? feats[u * KT + j] : 0.0f;

    float fv = 0.0f;
    const int Tmain = T & ~(PF - 1);

    for (int t = 0; t < Tmain; t += PF) {
#pragma unroll
        for (int u = 0; u < PF; u++) {
            float s[16];
#pragma unroll
            for (int p = 0; p < 16; p++)
                s[p] = __shfl_sync(MASK, fv, p) + a[p];
            // exact max tree (order-independent for fp max)
#pragma unroll
            for (int w = 8; w >= 1; w >>= 1)
#pragma unroll
                for (int p = 0; p < w; p++)
                    s[p] = fmaxf(s[p], s[p + w]);
            fv = s[0] + fq[u];
            g_fv[(t + u) * KT + j] = fv;
            int nt = t + u + PF;
            if (nt < T) fq[u] = feats[nt * KT + j];
        }
    }
    // tail (T not multiple of PF)
    for (int t = Tmain; t < T; t++) {
        float s[16];
#pragma unroll
        for (int p = 0; p < 16; p++)
            s[p] = __shfl_sync(MASK, fv, p) + a[p];
#pragma unroll
        for (int w = 8; w >= 1; w >>= 1)
#pragma unroll
            for (int p = 0; p < w; p++)
                s[p] = fmaxf(s[p], s[p + w]);
        fv = s[0] + feats[t * KT + j];
        g_fv[t * KT + j] = fv;
    }
}

// ---------------------------------------------------------------------------
// K2: backpointers, grid-parallel. Thread handles (t, i).
// Ascending scan with strict '>' keeps the FIRST max (jnp.argmax semantics).
// Scores recomputed with the identical single FADD -> bit-exact.
// ---------------------------------------------------------------------------
__global__ void k_bp(const float* __restrict__ trans, int T)
{
    int idx = blockIdx.x * blockDim.x + threadIdx.x;
    if (idx >= T * KT) return;
    int t = idx >> 4;
    int i = idx & 15;

    float pv[16];
    if (t == 0) {
#pragma unroll
        for (int p = 0; p < 16; p++) pv[p] = 0.0f;
    } else {
        const float4* row = reinterpret_cast<const float4*>(g_fv + (size_t)(t - 1) * KT);
#pragma unroll
        for (int q = 0; q < 4; q++) {
            float4 v = row[q];
            pv[4 * q + 0] = v.x; pv[4 * q + 1] = v.y;
            pv[4 * q + 2] = v.z; pv[4 * q + 3] = v.w;
        }
    }

    float a[16];
#pragma unroll
    for (int q = 0; q < 4; q++) {
        float4 v = reinterpret_cast<const float4*>(trans)[i * 4 + q];
        a[4 * q + 0] = v.x; a[4 * q + 1] = v.y;
        a[4 * q + 2] = v.z; a[4 * q + 3] = v.w;
    }

    float best = pv[0] + a[0];
    int bi = 0;
#pragma unroll
    for (int p = 1; p < 16; p++) {
        float sc = pv[p] + a[p];
        if (sc > best) { best = sc; bi = p; }
    }
    g_bp[idx] = (unsigned char)bi;
}

// ---------------------------------------------------------------------------
// K3: per-chunk backward chase of all 16 exit-tag hypotheses.
//   path16[s+tt][h] = bp-chase value given z_{chunk_last} = h.
//   comp[c][h] = z at last index of previous chunk.
// ---------------------------------------------------------------------------
__global__ void k_chunk(int T)
{
    __shared__ __align__(16) unsigned char sbp[CHUNK * KT];   // 16 KB
    int c = blockIdx.x;
    int s = c * CHUNK;
    int L = min(CHUNK, T - s);

    const int4* src = reinterpret_cast<const int4*>(g_bp + (size_t)s * KT);
    int4* dst = reinterpret_cast<int4*>(sbp);
    for (int i = threadIdx.x; i < L; i += blockDim.x) dst[i] = src[i];
    __syncthreads();

    if (threadIdx.x < 16) {
        int cur = threadIdx.x;                 // hypothesis: z at chunk last idx
        for (int tt = L - 1; tt >= 0; tt--) {
            cur = sbp[tt * KT + cur];
            g_p16[(size_t)(s + tt) * KT + threadIdx.x] = (unsigned char)cur;
        }
        g_comp[c * KT + threadIdx.x] = (unsigned char)cur;
    }
}

// ---------------------------------------------------------------------------
// K3b: compose chunk maps right-to-left. Z starts at argmax(final fv)
// (first-max). seed[c] = the hypothesis chunk c must use.
// ---------------------------------------------------------------------------
__global__ void k_seed(int T, int C)
{
    __shared__ __align__(16) unsigned char sc[NCHUNK_MAX * KT];
    for (int i = threadIdx.x; i < C * KT; i += blockDim.x) sc[i] = g_comp[i];
    __syncthreads();

    if (threadIdx.x == 0) {
        const float* f = g_fv + (size_t)(T - 1) * KT;
        float best = f[0];
        int Z = 0;
#pragma unroll
        for (int i = 1; i < 16; i++) {
            float v = f[i];
            if (v > best) { best = v; Z = i; }
        }
        for (int c = C - 1; c >= 0; c--) {
            g_seed[c] = (unsigned char)Z;
            Z = sc[c * KT + Z];
        }
    }
}

// ---------------------------------------------------------------------------
// K4: final select.  out[t] = (float) path16[t][ seed[chunk(t)] ]
// Output written as FLOAT32 tag values (harness output dtype).
// ---------------------------------------------------------------------------
__global__ void k_out(float* __restrict__ out, int T)
{
    int t = blockIdx.x * blockDim.x + threadIdx.x;
    if (t < T) {
        int h = g_seed[t / CHUNK];
        out[t] = (float)g_p16[(size_t)t * KT + h];
    }
}

// ---------------------------------------------------------------------------
extern "C" void kernel_launch(void* const* d_in, const int* in_sizes, int n_in,
                              void* d_out, int out_size)
{
    // Input autodetect: transitions is the 16x16=256-element tensor,
    // sentence is the large [1,T,16] tensor. Order-independent.
    int fi = 0;                                    // index of sentence (feats)
    if (n_in >= 2 && in_sizes[1] > in_sizes[0]) fi = 1;
    const float* feats = (const float*)d_in[fi];
    const float* trans = (const float*)d_in[1 - fi];

    int T = in_sizes[fi] / KT;
    if (T > T_MAX) T = T_MAX;
    if (out_size > 0 && out_size < T) T = out_size;  // out has exactly T elems
    if (T < 1) return;
    int C = (T + CHUNK - 1) / CHUNK;

    k_chain<<<1, 16>>>(feats, trans, T);
    k_bp<<<(T * KT + 255) / 256, 256>>>(trans, T);
    k_chunk<<<C, 128>>>(T);
    k_seed<<<1, 128>>>(T, C);
    k_out<<<(T + 255) / 256, 256>>>((float*)d_out, T);
}

// round 9
// speedup vs baseline: 1.0421x; 1.0421x over previous
#include <cuda_runtime.h>
#include <cstdint>

// ---------------------------------------------------------------------------
// CRF Viterbi decode, K=16 tags, T up to 1,000,000 steps.
//
// Pipeline:
//   K1 k_chain : sequential bit-exact forward recurrence. 32 lanes:
//                lanes j and j+16 cooperate on tag j (8 predecessors each),
//                cutting broadcast shuffles 16 -> 8 (+1 combine bfly).
//   K2 k_bp    : grid-parallel backpointers from fv trace (first-max argmax).
//   K3 k_chunk : per-chunk 16-hypothesis backward chase -> path16 + comp maps.
//   K3b k_seed : sequential composition of chunk maps (tiny), picks seeds.
//   K4 k_out   : parallel select of final path, written as FLOAT32.
//
// Inputs autodetected by element count: 256-element tensor = transitions
// [16,16]; large tensor = sentence [1,T,16].
// ---------------------------------------------------------------------------

#define T_MAX   1000000
#define KT      16
#define CHUNK   1024
#define NCHUNK_MAX ((T_MAX + CHUNK - 1) / CHUNK)   // 977
#define PF      16                                  // feat prefetch depth

__device__ __align__(16) float         g_fv[(size_t)T_MAX * KT];   // 64 MB
__device__ __align__(16) unsigned char g_bp[(size_t)T_MAX * KT];   // 16 MB
__device__ __align__(16) unsigned char g_p16[(size_t)T_MAX * KT];  // 16 MB
__device__ __align__(16) unsigned char g_comp[NCHUNK_MAX * KT];
__device__ __align__(16) unsigned char g_seed[NCHUNK_MAX];

// ---------------------------------------------------------------------------
// K1: sequential value chain, 1 warp of 32 lanes.
// Lane L: j = L&15 (tag), h = L>>4 (predecessor half).
//   candidates c[p'] = fv[h*8+p'] + A[j][h*8+p']   (one FADD each, bit-exact)
//   half-max via 3-level tree, pair-combine via shfl.xor(16),
//   fv[j] = max + feat[j]  (one FADD, bit-exact).
// fv stays replicated in both lanes of each pair.
// ---------------------------------------------------------------------------
__global__ void __launch_bounds__(32, 1)
k_chain(const float* __restrict__ feats, const float* __restrict__ trans, int T)
{
    const int L  = threadIdx.x;      // 0..31
    const int j  = L & 15;           // tag
    const int h  = L >> 4;           // half: 0 -> prev 0..7, 1 -> prev 8..15
    const int hb = h * 8;
    const unsigned FULL = 0xFFFFFFFFu;

    // A[j][hb .. hb+7] -> registers (two float4 loads)
    float a[8];
    {
        float4 v0 = reinterpret_cast<const float4*>(trans)[j * 4 + h * 2 + 0];
        float4 v1 = reinterpret_cast<const float4*>(trans)[j * 4 + h * 2 + 1];
        a[0] = v0.x; a[1] = v0.y; a[2] = v0.z; a[3] = v0.w;
        a[4] = v1.x; a[5] = v1.y; a[6] = v1.z; a[7] = v1.w;
    }

    // Loop-invariant shuffle source lanes: hb+0 .. hb+7
    int src[8];
#pragma unroll
    for (int p = 0; p < 8; p++) src[p] = hb + p;

    // Feat software pipeline: PF steps ahead (> DRAM latency).
    // Both halves load feat[j] (same 64B line, coalesces to one request).
    float fq[PF];
#pragma unroll
    for (int u = 0; u < PF; u++)
        fq[u] = (u < T) ? feats[u * KT + j] : 0.0f;

    float fv = 0.0f;                 // fv[j], replicated in lanes j and j+16
    const int Tmain = T & ~(PF - 1);

    for (int t = 0; t < Tmain; t += PF) {
#pragma unroll
        for (int u = 0; u < PF; u++) {
            float c[8];
#pragma unroll
            for (int p = 0; p < 8; p++)
                c[p] = __shfl_sync(FULL, fv, src[p]) + a[p];
            // 3-level exact max tree over this half's 8 candidates
            c[0] = fmaxf(c[0], c[4]); c[1] = fmaxf(c[1], c[5]);
            c[2] = fmaxf(c[2], c[6]); c[3] = fmaxf(c[3], c[7]);
            c[0] = fmaxf(c[0], c[2]); c[1] = fmaxf(c[1], c[3]);
            c[0] = fmaxf(c[0], c[1]);
            // combine halves (exact max, order-independent)
            float oth = __shfl_xor_sync(FULL, c[0], 16);
            fv = fmaxf(c[0], oth) + fq[u];
            if (h == 0) g_fv[(t + u) * KT + j] = fv;
            int nt = t + u + PF;
            if (nt < T) fq[u] = feats[nt * KT + j];
        }
    }
    // tail (T not multiple of PF)
    for (int t = Tmain; t < T; t++) {
        float c[8];
#pragma unroll
        for (int p = 0; p < 8; p++)
            c[p] = __shfl_sync(FULL, fv, src[p]) + a[p];
        c[0] = fmaxf(c[0], c[4]); c[1] = fmaxf(c[1], c[5]);
        c[2] = fmaxf(c[2], c[6]); c[3] = fmaxf(c[3], c[7]);
        c[0] = fmaxf(c[0], c[2]); c[1] = fmaxf(c[1], c[3]);
        c[0] = fmaxf(c[0], c[1]);
        float oth = __shfl_xor_sync(FULL, c[0], 16);
        fv = fmaxf(c[0], oth) + feats[t * KT + j];
        if (h == 0) g_fv[t * KT + j] = fv;
    }
}

// ---------------------------------------------------------------------------
// K2: backpointers, grid-parallel. Thread handles (t, i).
// Ascending scan with strict '>' keeps the FIRST max (jnp.argmax semantics).
// Scores recomputed with the identical single FADD -> bit-exact.
// ---------------------------------------------------------------------------
__global__ void k_bp(const float* __restrict__ trans, int T)
{
    int idx = blockIdx.x * blockDim.x + threadIdx.x;
    if (idx >= T * KT) return;
    int t = idx >> 4;
    int i = idx & 15;

    float pv[16];
    if (t == 0) {
#pragma unroll
        for (int p = 0; p < 16; p++) pv[p] = 0.0f;
    } else {
        const float4* row = reinterpret_cast<const float4*>(g_fv + (size_t)(t - 1) * KT);
#pragma unroll
        for (int q = 0; q < 4; q++) {
            float4 v = row[q];
            pv[4 * q + 0] = v.x; pv[4 * q + 1] = v.y;
            pv[4 * q + 2] = v.z; pv[4 * q + 3] = v.w;
        }
    }

    float a[16];
#pragma unroll
    for (int q = 0; q < 4; q++) {
        float4 v = reinterpret_cast<const float4*>(trans)[i * 4 + q];
        a[4 * q + 0] = v.x; a[4 * q + 1] = v.y;
        a[4 * q + 2] = v.z; a[4 * q + 3] = v.w;
    }

    float best = pv[0] + a[0];
    int bi = 0;
#pragma unroll
    for (int p = 1; p < 16; p++) {
        float sc = pv[p] + a[p];
        if (sc > best) { best = sc; bi = p; }
    }
    g_bp[idx] = (unsigned char)bi;
}

// ---------------------------------------------------------------------------
// K3: per-chunk backward chase of all 16 exit-tag hypotheses.
// ---------------------------------------------------------------------------
__global__ void k_chunk(int T)
{
    __shared__ __align__(16) unsigned char sbp[CHUNK * KT];   // 16 KB
    int c = blockIdx.x;
    int s = c * CHUNK;
    int L = min(CHUNK, T - s);

    const int4* src = reinterpret_cast<const int4*>(g_bp + (size_t)s * KT);
    int4* dst = reinterpret_cast<int4*>(sbp);
    for (int i = threadIdx.x; i < L; i += blockDim.x) dst[i] = src[i];
    __syncthreads();

    if (threadIdx.x < 16) {
        int cur = threadIdx.x;                 // hypothesis: z at chunk last idx
        for (int tt = L - 1; tt >= 0; tt--) {
            cur = sbp[tt * KT + cur];
            g_p16[(size_t)(s + tt) * KT + threadIdx.x] = (unsigned char)cur;
        }
        g_comp[c * KT + threadIdx.x] = (unsigned char)cur;
    }
}

// ---------------------------------------------------------------------------
// K3b: compose chunk maps right-to-left. Z starts at argmax(final fv).
// ---------------------------------------------------------------------------
__global__ void k_seed(int T, int C)
{
    __shared__ __align__(16) unsigned char sc[NCHUNK_MAX * KT];
    for (int i = threadIdx.x; i < C * KT; i += blockDim.x) sc[i] = g_comp[i];
    __syncthreads();

    if (threadIdx.x == 0) {
        const float* f = g_fv + (size_t)(T - 1) * KT;
        float best = f[0];
        int Z = 0;
#pragma unroll
        for (int i = 1; i < 16; i++) {
            float v = f[i];
            if (v > best) { best = v; Z = i; }
        }
        for (int c = C - 1; c >= 0; c--) {
            g_seed[c] = (unsigned char)Z;
            Z = sc[c * KT + Z];
        }
    }
}

// ---------------------------------------------------------------------------
// K4: final select.  out[t] = (float) path16[t][ seed[chunk(t)] ]
// ---------------------------------------------------------------------------
__global__ void k_out(float* __restrict__ out, int T)
{
    int t = blockIdx.x * blockDim.x + threadIdx.x;
    if (t < T) {
        int h = g_seed[t / CHUNK];
        out[t] = (float)g_p16[(size_t)t * KT + h];
    }
}

// ---------------------------------------------------------------------------
extern "C" void kernel_launch(void* const* d_in, const int* in_sizes, int n_in,
                              void* d_out, int out_size)
{
    // Input autodetect: transitions is the 256-element tensor,
    // sentence is the large [1,T,16] tensor. Order-independent.
    int fi = 0;
    if (n_in >= 2 && in_sizes[1] > in_sizes[0]) fi = 1;
    const float* feats = (const float*)d_in[fi];
    const float* trans = (const float*)d_in[1 - fi];

    int T = in_sizes[fi] / KT;
    if (T > T_MAX) T = T_MAX;
    if (out_size > 0 && out_size < T) T = out_size;
    if (T < 1) return;
    int C = (T + CHUNK - 1) / CHUNK;

    k_chain<<<1, 32>>>(feats, trans, T);
    k_bp<<<(T * KT + 255) / 256, 256>>>(trans, T);
    k_chunk<<<C, 128>>>(T);
    k_seed<<<1, 128>>>(T, C);
    k_out<<<(T + 255) / 256, 256>>>((float*)d_out, T);
}